// round 17
// baseline (speedup 1.0000x reference)
#include <cuda_runtime.h>
#include <cuda_fp16.h>
#include <cstdint>
#include <cstring>

// LSM_IniReconNet fused two-stage GEMM, fp16 mma.sync m16n8k16 (fp32 accum).
//   stage 1: meas[64,256] = P[64,1024] @ Ws^T   (Ws [256,1024] row-major)
//   stage 2: Y[64,1024]   = meas @ Wi^T         (Wi [1024,256] row-major)
// R16 + latency round: stage-1 K-chunk widened to 64 (16 barriers instead of
// 32, 4 prefetch LDG.128s in flight), stage-2 B software pipeline deepened to
// 2 k16-steps (~300cyc > L2 latency). Weights pre-converted to __device__
// half arrays; B fragments are single coalesced LDG.64s. 256 CTAs x 256
// threads, 2 CTAs/SM.

#define N_THREADS 256
#define N_CTA 256

// smem layout (bytes)
#define MH_STR   1088                 // 68 x 16B units/row; 68 % 8 == 4
#define MH_BYTES (32 * MH_STR)        // 34816
#define A_STR    320                  // 256B data + 64 pad; 320 % 128 == 64
#define A_BUF    (32 * A_STR)         // 10240
#define SMEM_BYTES (MH_BYTES + 2 * A_BUF)   // 55296

__device__ __half g_wsh[256 * 1024];
__device__ __half g_wih[1024 * 256];

__device__ __forceinline__ uint32_t h2u(__half2 h) {
    uint32_t u;
    memcpy(&u, &h, 4);
    return u;
}

__global__ void cvt_weights(const float* __restrict__ ws,
                            const float* __restrict__ wi)
{
    int i = blockIdx.x * blockDim.x + threadIdx.x;    // 0..131071
    const bool first = (i < 65536);
    const float4 f = first ? reinterpret_cast<const float4*>(ws)[i]
                           : reinterpret_cast<const float4*>(wi)[i - 65536];
    __half2 h0 = __floats2half2_rn(f.x, f.y);
    __half2 h1 = __floats2half2_rn(f.z, f.w);
    __half2* dst = first ? reinterpret_cast<__half2*>(g_wsh) + 2 * i
                         : reinterpret_cast<__half2*>(g_wih) + 2 * (i - 65536);
    dst[0] = h0;
    dst[1] = h1;
}

__device__ __forceinline__ void mma_f16(float c[4], const uint32_t a[4],
                                        uint32_t b0, uint32_t b1) {
    asm volatile(
        "mma.sync.aligned.m16n8k16.row.col.f32.f16.f16.f32 "
        "{%0,%1,%2,%3}, {%4,%5,%6,%7}, {%8,%9}, {%0,%1,%2,%3};"
        : "+f"(c[0]), "+f"(c[1]), "+f"(c[2]), "+f"(c[3])
        : "r"(a[0]), "r"(a[1]), "r"(a[2]), "r"(a[3]), "r"(b0), "r"(b1));
}

__global__ void __launch_bounds__(N_THREADS, 2)
lsm_fused_kernel(const float* __restrict__ x, float* __restrict__ y)
{
    extern __shared__ char sm[];
    char* MH = sm;                 // meas, half, 32 grow-rows x 68 units
    char* AB = sm + MH_BYTES;      // 2 x A buffer (half, 64-k chunk)

    const int tid  = threadIdx.x;
    const int w    = tid >> 5;     // warp owns n-cols [w*32, +32)
    const int lane = tid & 31;
    const int g  = lane >> 2;
    const int tc = lane & 3;
    const int p0 = blockIdx.x * 64;

    // ---- A loader precompute: 4 float4 / thread / 64-k chunk ----
    // v = tid + i*256: p = v>>4 (patch), u = v&15: rp = u>>3 (row parity),
    // kq = u&7 (float4 within 32-wide row). Chunk kc2 covers patch rows
    // {2kc2, 2kc2+1}. 16B unit: [r:(k0..k3) | r+8:(k0..k3)] per k4 group.
    size_t a_goff[4]; int a_soff[4];
    #pragma unroll
    for (int i = 0; i < 4; ++i) {
        int v = tid + i * 256;
        int p = v >> 4, u = v & 15;
        int rp = u >> 3, kq = u & 7;
        int gp = p0 + p;
        int b = gp >> 10, rem = gp & 1023, bh = rem >> 5, bw = rem & 31;
        a_goff[i] = ((size_t)b << 20) + (size_t)(bh << 5) * 1024 + (bw << 5)
                  + (size_t)rp * 1024 + (kq << 2);
        int grow = (p >> 4) * 8 + (p & 7);
        a_soff[i] = grow * A_STR + (rp * 2 + (kq >> 2)) * 64
                  + (kq & 3) * 16 + 8 * ((p >> 3) & 1);
    }

    // half-weight base pointers: row = w*32 + nf*8 + g, inner 4*tc
    const __half* wsp = g_wsh + (size_t)(w * 32 + g) * 1024 + 4 * tc;
    const __half* wip = g_wih + (size_t)(w * 32 + g) * 256 + 4 * tc;

    // ---- prologue: preload B(T=0); stage A chunk 0 ----
    uint2 Bc[4];
    #pragma unroll
    for (int nf = 0; nf < 4; ++nf)
        Bc[nf] = *reinterpret_cast<const uint2*>(wsp + nf * 8192);
    #pragma unroll
    for (int i = 0; i < 4; ++i) {
        const float4 f = *reinterpret_cast<const float4*>(x + a_goff[i]);
        uint2 hv;
        hv.x = h2u(__floats2half2_rn(f.x, f.y));
        hv.y = h2u(__floats2half2_rn(f.z, f.w));
        *reinterpret_cast<uint2*>(AB + a_soff[i]) = hv;
    }
    __syncthreads();

    // ================= Stage 1 =================
    float acc[4][4][4];
    #pragma unroll
    for (int i = 0; i < 4; i++)
        #pragma unroll
        for (int j = 0; j < 4; j++)
            #pragma unroll
            for (int k = 0; k < 4; k++) acc[i][j][k] = 0.f;

    for (int kc2 = 0; kc2 < 16; ++kc2) {       // 64-k chunks
        float4 pf[4];
        const bool pre = (kc2 < 15);
        if (pre) {
            #pragma unroll
            for (int i = 0; i < 4; ++i)
                pf[i] = *reinterpret_cast<const float4*>(
                    x + a_goff[i] + (size_t)(kc2 + 1) * 2048);
        }

        const char* Ab = AB + (kc2 & 1) * A_BUF;

        #pragma unroll
        for (int ks = 0; ks < 4; ++ks) {       // 4 x k16 per chunk
            uint2 bb[4];
            #pragma unroll
            for (int nf = 0; nf < 4; ++nf) bb[nf] = Bc[nf];
            // issue next B block (flattened T = kc2*4 + ks, prefetch T+1)
            {
                const int Tn = (kc2 * 4 + ks + 1) & 63;
                #pragma unroll
                for (int nf = 0; nf < 4; ++nf)
                    Bc[nf] = *reinterpret_cast<const uint2*>(
                        wsp + Tn * 16 + nf * 8192);
            }
            #pragma unroll
            for (int mf = 0; mf < 4; ++mf) {
                const uint4 wv = *reinterpret_cast<const uint4*>(
                    Ab + (mf * 8 + g) * A_STR + (ks * 4 + tc) * 16);
                uint32_t a4[4] = {wv.x, wv.z, wv.y, wv.w};
                #pragma unroll
                for (int nf = 0; nf < 4; ++nf)
                    mma_f16(acc[mf][nf], a4, bb[nf].x, bb[nf].y);
            }
        }

        if (pre) {
            char* Aw = AB + ((kc2 + 1) & 1) * A_BUF;
            #pragma unroll
            for (int i = 0; i < 4; ++i) {
                uint2 hv;
                hv.x = h2u(__floats2half2_rn(pf[i].x, pf[i].y));
                hv.y = h2u(__floats2half2_rn(pf[i].z, pf[i].w));
                *reinterpret_cast<uint2*>(Aw + a_soff[i]) = hv;
            }
        }
        __syncthreads();
    }

    // preload stage-2 B blocks T=0,1 (2-deep pipeline)
    uint2 Bc2[2][4];
    #pragma unroll
    for (int nf = 0; nf < 4; ++nf) {
        Bc2[0][nf] = *reinterpret_cast<const uint2*>(wip + nf * 2048);
        Bc2[1][nf] = *reinterpret_cast<const uint2*>(wip + 16 + nf * 2048);
    }

    // ---- dump meas to MH (half), at permuted slot positions ----
    #pragma unroll
    for (int mf = 0; mf < 4; ++mf) {
        #pragma unroll
        for (int nf = 0; nf < 4; ++nf) {
            int ub = (mf * 8 + g) * MH_STR
                   + ((w * 2 + (nf >> 1)) * 4 + (nf & 1) * 2 + (tc >> 1)) * 16
                   + 4 * (tc & 1);
            *reinterpret_cast<__half2*>(MH + ub) =
                __floats2half2_rn(acc[mf][nf][0], acc[mf][nf][1]);   // r
            *reinterpret_cast<__half2*>(MH + ub + 8) =
                __floats2half2_rn(acc[mf][nf][2], acc[mf][nf][3]);   // r+8
        }
    }
    __syncthreads();

    // ================= Stage 2 (no barriers, 2-deep B pipeline) ==========
    for (int nc = 0; nc < 4; ++nc) {
        float acc2[4][4][4];
        #pragma unroll
        for (int i = 0; i < 4; i++)
            #pragma unroll
            for (int j = 0; j < 4; j++)
                #pragma unroll
                for (int k = 0; k < 4; k++) acc2[i][j][k] = 0.f;

        #pragma unroll 2
        for (int ks = 0; ks < 16; ++ks) {    // 16 x k16 over s=256
            uint2 bb[4];
            #pragma unroll
            for (int nf = 0; nf < 4; ++nf) bb[nf] = Bc2[ks & 1][nf];
            // prefetch T+2 (flattened T = nc*16 + ks)
            {
                const int Tn = (nc * 16 + ks + 2) & 63;
                const __half* nw = wip + (size_t)(Tn >> 4) * 65536 + (Tn & 15) * 16;
                #pragma unroll
                for (int nf = 0; nf < 4; ++nf)
                    Bc2[ks & 1][nf] =
                        *reinterpret_cast<const uint2*>(nw + nf * 2048);
            }
            #pragma unroll
            for (int mf = 0; mf < 4; ++mf) {
                const uint4 wv = *reinterpret_cast<const uint4*>(
                    MH + (mf * 8 + g) * MH_STR + (ks * 4 + tc) * 16);
                uint32_t a4[4] = {wv.x, wv.z, wv.y, wv.w};
                #pragma unroll
                for (int nf = 0; nf < 4; ++nf)
                    mma_f16(acc2[mf][nf], a4, bb[nf].x, bb[nf].y);
            }
        }

        // epilogue: c = nc*256 + w*32 + nf*8 + 2tc -> kh = nc*8 + w
        const int kh = nc * 8 + w;
        #pragma unroll
        for (int mf = 0; mf < 4; ++mf) {
            #pragma unroll
            for (int half_ = 0; half_ < 2; ++half_) {
                int r   = mf * 16 + g + 8 * half_;
                int gp  = p0 + r;
                int b   = gp >> 10;
                int rem = gp & 1023;
                int bh = rem >> 5, bw = rem & 31;
                float* yb = y + ((size_t)b << 20)
                              + (size_t)((bh << 5) + kh) * 1024 + (bw << 5);
                #pragma unroll
                for (int nf = 0; nf < 4; ++nf) {
                    float2 v2;
                    v2.x = acc2[mf][nf][half_ * 2 + 0];
                    v2.y = acc2[mf][nf][half_ * 2 + 1];
                    *reinterpret_cast<float2*>(yb + nf * 8 + 2 * tc) = v2;
                }
            }
        }
    }
}

extern "C" void kernel_launch(void* const* d_in, const int* in_sizes, int n_in,
                              void* d_out, int out_size)
{
    const float* x  = (const float*)d_in[0];   // [16,1,1024,1024]
    const float* ws = (const float*)d_in[1];   // [256,1024]
    const float* wi = (const float*)d_in[2];   // [1024,256]
    float* y = (float*)d_out;                  // [16,1,1024,1024]

    cvt_weights<<<512, 256>>>(ws, wi);
    cudaFuncSetAttribute(lsm_fused_kernel,
                         cudaFuncAttributeMaxDynamicSharedMemorySize, SMEM_BYTES);
    lsm_fused_kernel<<<N_CTA, N_THREADS, SMEM_BYTES>>>(x, y);
}